// round 14
// baseline (speedup 1.0000x reference)
#include <cuda_runtime.h>
#include <cuda_bf16.h>
#include <cstdint>

#define B_   16
#define C_   64
#define H_   64
#define W_   64
#define N_   4096
#define M_   1024
#define D8   8
#define D2   32
#define CH48 48

// Device scratch (no cudaMalloc allowed)
__device__ uint32_t d_thp[B_ * 8 * N_];          // theta pre-scaled tf32 bits
__device__ uint32_t d_phip[B_ * M_ * 8];         // phi pre-packed tf32 frag slots
__device__ uint32_t d_gp[B_ * D2 * M_ / 2];      // g pre-packed bf16x2 frag slots

// ---- f32x2 packed helpers ---------------------------------------------------
__device__ __forceinline__ void ffma2(unsigned long long& d,
                                      unsigned long long a,
                                      unsigned long long b) {
    asm("fma.rn.f32x2 %0, %1, %2, %0;" : "+l"(d) : "l"(a), "l"(b));
}
__device__ __forceinline__ unsigned long long pack_ff(float lo, float hi) {
    unsigned long long r;
    asm("mov.b64 %0, {%1,%2};" : "=l"(r) : "f"(lo), "f"(hi));
    return r;
}
__device__ __forceinline__ void unpack_ff(unsigned long long v, float& lo, float& hi) {
    asm("mov.b64 {%0,%1}, %2;" : "=f"(lo), "=f"(hi) : "l"(v));
}

// ---- mma wrappers (baseline PTX, legal on plain sm_103) ----------------------
__device__ __forceinline__ void mma16816(float& d0, float& d1, float& d2, float& d3,
                                         uint32_t a0, uint32_t a1, uint32_t a2, uint32_t a3,
                                         uint32_t b0, uint32_t b1) {
    asm volatile(
        "mma.sync.aligned.m16n8k16.row.col.f32.bf16.bf16.f32 "
        "{%0,%1,%2,%3}, {%4,%5,%6,%7}, {%8,%9}, {%0,%1,%2,%3};"
        : "+f"(d0), "+f"(d1), "+f"(d2), "+f"(d3)
        : "r"(a0), "r"(a1), "r"(a2), "r"(a3), "r"(b0), "r"(b1));
}
__device__ __forceinline__ void mma1688_tf32(float& d0, float& d1, float& d2, float& d3,
                                             uint32_t a0, uint32_t a1, uint32_t a2, uint32_t a3,
                                             uint32_t b0, uint32_t b1) {
    asm volatile(
        "mma.sync.aligned.m16n8k8.row.col.f32.tf32.tf32.f32 "
        "{%0,%1,%2,%3}, {%4,%5,%6,%7}, {%8,%9}, {%0,%1,%2,%3};"
        : "+f"(d0), "+f"(d1), "+f"(d2), "+f"(d3)
        : "r"(a0), "r"(a1), "r"(a2), "r"(a3), "r"(b0), "r"(b1));
}
__device__ __forceinline__ uint32_t to_tf32(float v) {
    uint32_t r;
    asm("cvt.rna.tf32.f32 %0, %1;" : "=r"(r) : "f"(v));
    return r;
}
__device__ __forceinline__ uint32_t bf16x2_of(float lo, float hi) {
    uint32_t r;
    asm("cvt.rn.bf16x2.f32 %0, %1, %2;" : "=r"(r) : "f"(hi), "f"(lo));
    return r;
}
__device__ __forceinline__ float ex2f(float v) {
    float r;
    asm("ex2.approx.f32 %0, %1;" : "=f"(r) : "f"(v));
    return r;
}

// ---------------------------------------------------------------------------
// P1: SINGLE-PASS fused conv1x1 + 2x2 maxpool + frag packing.
// Each thread: ONE position, ALL 48 channels (24 packed u64 accumulators).
// Lane layout: lanes 0-15 = row h cols w0..w0+15, lanes 16-31 = row h+1.
//   pool = fmax(shfl_xor 1) then fmax(shfl_xor 16)  -> all lanes hold quad max
//   g (m, m+1) pairing = shfl_down 2 on writer lanes
// x is read ONCE (16 MB vs 32 MB in the two-pass version).
// theta stored pre-scaled by log2e as tf32 bits (main loads fragments bare).
// ---------------------------------------------------------------------------
__global__ void __launch_bounds__(256) convpool_kernel(
    const float* __restrict__ x,
    const float* __restrict__ w_theta, const float* __restrict__ b_theta,
    const float* __restrict__ w_phi,   const float* __restrict__ b_phi,
    const float* __restrict__ w_g,     const float* __restrict__ b_g)
{
    __shared__ float w_s[C_ * CH48];     // transposed: w_s[c][ch], 12 KB
    __shared__ float bias_s[CH48];
    int tid = threadIdx.x;

    for (int i = tid; i < C_ * CH48; i += 256) {
        int c = i / CH48, ch = i % CH48;
        float v;
        if (ch < 8)       v = w_theta[ch * C_ + c];
        else if (ch < 16) v = w_phi[(ch - 8) * C_ + c];
        else              v = w_g[(ch - 16) * C_ + c];
        w_s[i] = v;
    }
    if (tid < CH48) {
        bias_s[tid] = (tid < 8) ? b_theta[tid]
                    : (tid < 16 ? b_phi[tid - 8] : b_g[tid - 16]);
    }
    __syncthreads();

    int warp = tid >> 5, lane = tid & 31;
    int bi  = blockIdx.x;            // 0..255
    int b   = bi >> 4;
    int sub = bi & 15;               // 4 rows of this batch
    int h    = sub * 4 + 2 * (warp >> 2) + (lane >> 4);
    int wcol = (warp & 3) * 16 + (lane & 15);
    int n    = h * W_ + wcol;

    unsigned long long acc[24];      // 48 channels, 2 per u64
    #pragma unroll
    for (int j = 0; j < 24; j++) acc[j] = pack_ff(bias_s[2 * j], bias_s[2 * j + 1]);

    const float* xb = x + ((size_t)b * C_) * N_ + n;
    #pragma unroll 8
    for (int c = 0; c < C_; c++) {
        float xv = xb[(size_t)c * N_];
        unsigned long long xv2 = pack_ff(xv, xv);
        const float4* wrow = (const float4*)(w_s + c * CH48);
        #pragma unroll
        for (int j = 0; j < 12; j++) {
            float4 w4 = wrow[j];
            ffma2(acc[2 * j],     xv2, pack_ff(w4.x, w4.y));
            ffma2(acc[2 * j + 1], xv2, pack_ff(w4.z, w4.w));
        }
    }

    // theta (ch 0..7): store per-position, pre-scaled by log2e, tf32 bits
    {
        uint32_t* tb = d_thp + (size_t)b * 8 * N_ + n;
        const float sc = 1.4426950408889634f;
        #pragma unroll
        for (int j = 0; j < 4; j++) {
            float v0, v1;
            unpack_ff(acc[j], v0, v1);
            tb[(size_t)(2 * j) * N_]     = to_tf32(v0 * sc);
            tb[(size_t)(2 * j + 1) * N_] = to_tf32(v1 * sc);
        }
    }

    // pooled coordinates
    int mh = h >> 1;                 // valid on writer lanes (lane<16 -> h even)
    int mw = wcol >> 1;
    int m  = mh * 32 + mw;
    int r  = m & 15;
    uint32_t gslot = (uint32_t)((m & ~15) * 2 + ((r >> 1) & 3) * 8 + (r >> 3) * 4);
    bool phi_writer = (lane < 16) && ((lane & 1) == 0);
    bool g_writer   = (lane < 16) && ((lane & 3) == 0);

    // phi (ch 8..15) -> pooled tf32 frag slots
    #pragma unroll
    for (int j = 4; j < 8; j++) {
        float v0, v1;
        unpack_ff(acc[j], v0, v1);
        #pragma unroll
        for (int s = 0; s < 2; s++) {
            float v = s ? v1 : v0;
            v = fmaxf(v, __shfl_xor_sync(0xffffffffu, v, 1));
            v = fmaxf(v, __shfl_xor_sync(0xffffffffu, v, 16));
            if (phi_writer) {
                int d = 2 * j + s - 8;
                d_phip[b * 8192 + m * 8 + (d & 3) * 2 + (d >> 2)] = to_tf32(v);
            }
        }
    }

    // g (ch 16..47) -> pooled bf16x2 pair slots
    #pragma unroll
    for (int j = 8; j < 24; j++) {
        float v0, v1;
        unpack_ff(acc[j], v0, v1);
        #pragma unroll
        for (int s = 0; s < 2; s++) {
            float v = s ? v1 : v0;
            v = fmaxf(v, __shfl_xor_sync(0xffffffffu, v, 1));
            v = fmaxf(v, __shfl_xor_sync(0xffffffffu, v, 16));
            float vn = __shfl_down_sync(0xffffffffu, v, 2);   // pooled m+1
            if (g_writer) {
                int c = 2 * j + s - 16;
                __nv_bfloat162 hh = __floats2bfloat162_rn(v, vn);
                uint32_t byte = (uint32_t)(b * 32 + c) * 2048 + gslot;
                d_gp[byte >> 2] = *(uint32_t*)&hh;
            }
        }
    }
}

// ---------------------------------------------------------------------------
// Main kernel (R13 winner, unchanged except theta source = d_thp).
// ---------------------------------------------------------------------------
#define GS3    2080                         // smem g row stride bytes
#define OFF_G    0                          // 32*2080 = 66560
#define OFF_PHI  66560                      // 32768 -> 99328
#define OFF_WO   99328                      // 8192  -> 107520
#define OFF_BO   107520                     // 256   -> 107776
#define OFF_AG   0                          // alias G (dead after loop)
#define SMEM_REQ 107776

__global__ void __launch_bounds__(512, 2) attn_main_kernel(
    const float* __restrict__ x,
    const float* __restrict__ w_o,
    const float* __restrict__ b_o,
    const float* __restrict__ sigma,
    float* __restrict__ out)
{
    extern __shared__ char smp[];
    float* wo_s = (float*)(smp + OFF_WO);
    float* bo_s = (float*)(smp + OFF_BO);
    float* ag_s = (float*)(smp + OFF_AG);

    int tid   = threadIdx.x;
    int warp  = tid >> 5, lane = tid & 31;
    int b     = blockIdx.y;
    int qbase = blockIdx.x * 256;

    int q0 = warp * 16;
    int g  = lane >> 2;
    int tg = lane & 3;

    // theta A-fragments: bare LDGs of pre-converted tf32 bits
    const uint32_t* tsrc = d_thp + (size_t)b * 8 * N_ + qbase;
    uint32_t ta0 = tsrc[(size_t)tg * N_ + q0 + g];
    uint32_t ta1 = tsrc[(size_t)tg * N_ + q0 + g + 8];
    uint32_t ta2 = tsrc[(size_t)(tg + 4) * N_ + q0 + g];
    uint32_t ta3 = tsrc[(size_t)(tg + 4) * N_ + q0 + g + 8];

    // ---- setup: pure memcpy of pre-packed frag data ----
    {
        const uint4* gp = (const uint4*)(d_gp + (size_t)b * 16384);
        for (int i = tid; i < 4096; i += 512) {       // 65536 B
            int c = i >> 7, w = i & 127;
            *(uint4*)(smp + OFF_G + c * GS3 + w * 16) = gp[i];
        }
        const uint4* pp = (const uint4*)(d_phip + (size_t)b * 8192);
        for (int i = tid; i < 2048; i += 512)         // 32768 B
            *(uint4*)(smp + OFF_PHI + i * 16) = pp[i];
        const float4* w4 = (const float4*)w_o;
        float4* ws4 = (float4*)wo_s;
        for (int i = tid; i < 64 * 32 / 4; i += 512) ws4[i] = w4[i];
        if (tid < 64) bo_s[tid] = b_o[tid];
    }
    __syncthreads();

    float rs_lo = 0.f, rs_hi = 0.f;
    float acc[4][4];
    #pragma unroll
    for (int nt = 0; nt < 4; nt++)
        #pragma unroll
        for (int r = 0; r < 4; r++) acc[nt][r] = 0.f;

    // induction pointers (all other offsets are immediates)
    const char* pPhi = smp + OFF_PHI + g * 32 + tg * 8;
    const char* pG   = smp + OFF_G + g * GS3 + tg * 8;

    // ---- 64 units of 16 keys: full K per warp ----
    #pragma unroll 1
    for (int u = 0; u < 64; u++) {
        uint2 p0 = *(const uint2*)(pPhi);
        uint2 p1 = *(const uint2*)(pPhi + 256);
        uint2 g0 = *(const uint2*)(pG);
        uint2 g1 = *(const uint2*)(pG + 8 * GS3);
        uint2 g2 = *(const uint2*)(pG + 16 * GS3);
        uint2 g3 = *(const uint2*)(pG + 24 * GS3);
        pPhi += 512;
        pG   += 32;

        float e0 = 0.f, e1 = 0.f, e2 = 0.f, e3 = 0.f;
        mma1688_tf32(e0, e1, e2, e3, ta0, ta1, ta2, ta3, p0.x, p0.y);
        float f0 = 0.f, f1 = 0.f, f2 = 0.f, f3 = 0.f;
        mma1688_tf32(f0, f1, f2, f3, ta0, ta1, ta2, ta3, p1.x, p1.y);

        e0 = ex2f(e0); e1 = ex2f(e1); e2 = ex2f(e2); e3 = ex2f(e3);
        f0 = ex2f(f0); f1 = ex2f(f1); f2 = ex2f(f2); f3 = ex2f(f3);
        rs_lo += (e0 + e1) + (f0 + f1);
        rs_hi += (e2 + e3) + (f2 + f3);

        uint32_t a0 = bf16x2_of(e0, e1);
        uint32_t a1 = bf16x2_of(e2, e3);
        uint32_t a2 = bf16x2_of(f0, f1);
        uint32_t a3 = bf16x2_of(f2, f3);

        mma16816(acc[0][0], acc[0][1], acc[0][2], acc[0][3], a0, a1, a2, a3, g0.x, g0.y);
        mma16816(acc[1][0], acc[1][1], acc[1][2], acc[1][3], a0, a1, a2, a3, g1.x, g1.y);
        mma16816(acc[2][0], acc[2][1], acc[2][2], acc[2][3], a0, a1, a2, a3, g2.x, g2.y);
        mma16816(acc[3][0], acc[3][1], acc[3][2], acc[3][3], a0, a1, a2, a3, g3.x, g3.y);
    }

    // ---- complete rowsums via quad shuffle ----
    rs_lo += __shfl_xor_sync(0xffffffffu, rs_lo, 1);
    rs_lo += __shfl_xor_sync(0xffffffffu, rs_lo, 2);
    rs_hi += __shfl_xor_sync(0xffffffffu, rs_hi, 1);
    rs_hi += __shfl_xor_sync(0xffffffffu, rs_hi, 2);
    float inv_lo = 1.f / rs_lo;
    float inv_hi = 1.f / rs_hi;

    __syncthreads();   // all warps done reading G/PHI -> AG alias safe

    // normalize in registers, stage AG[q][c]
    #pragma unroll
    for (int nt = 0; nt < 4; nt++) {
        int c0 = nt * 8 + 2 * tg;
        ag_s[(q0 + g) * 36 + c0]         = acc[nt][0] * inv_lo;
        ag_s[(q0 + g) * 36 + c0 + 1]     = acc[nt][1] * inv_lo;
        ag_s[(q0 + g + 8) * 36 + c0]     = acc[nt][2] * inv_hi;
        ag_s[(q0 + g + 8) * 36 + c0 + 1] = acc[nt][3] * inv_hi;
    }
    __syncthreads();

    // ---- projection + residual epilogue (coalesced) ----
    float sig = sigma[0];
    int nl = tid & 255;
    int kh = tid >> 8;

    float ag[32];
    #pragma unroll
    for (int c4 = 0; c4 < 8; c4++) {
        float4 v = *(const float4*)(ag_s + nl * 36 + 4 * c4);
        ag[4 * c4 + 0] = v.x; ag[4 * c4 + 1] = v.y;
        ag[4 * c4 + 2] = v.z; ag[4 * c4 + 3] = v.w;
    }
    size_t xoff_base = ((size_t)b * C_ + kh * 32) * N_ + qbase + nl;
    #pragma unroll 4
    for (int kk = 0; kk < 32; kk++) {
        int k = kh * 32 + kk;
        float val = bo_s[k];
        const float4* wrow = (const float4*)(wo_s + k * 32);
        #pragma unroll
        for (int c4 = 0; c4 < 8; c4++) {
            float4 w4 = wrow[c4];
            val += w4.x * ag[4 * c4] + w4.y * ag[4 * c4 + 1]
                 + w4.z * ag[4 * c4 + 2] + w4.w * ag[4 * c4 + 3];
        }
        size_t off = xoff_base + (size_t)kk * N_;
        out[off] = x[off] + sig * val;
    }
}

// ---------------------------------------------------------------------------
extern "C" void kernel_launch(void* const* d_in, const int* in_sizes, int n_in,
                              void* d_out, int out_size)
{
    const float* x       = (const float*)d_in[0];
    const float* w_theta = (const float*)d_in[1];
    const float* b_theta = (const float*)d_in[2];
    const float* w_phi   = (const float*)d_in[3];
    const float* b_phi   = (const float*)d_in[4];
    const float* w_g     = (const float*)d_in[5];
    const float* b_g     = (const float*)d_in[6];
    const float* w_o     = (const float*)d_in[7];
    const float* b_o     = (const float*)d_in[8];
    const float* sigma   = (const float*)d_in[9];
    float* out = (float*)d_out;

    convpool_kernel<<<B_ * 16, 256>>>(x, w_theta, b_theta, w_phi, b_phi, w_g, b_g);

    cudaFuncSetAttribute(attn_main_kernel,
                         cudaFuncAttributeMaxDynamicSharedMemorySize, SMEM_REQ);
    attn_main_kernel<<<dim3(N_ / 256, B_), 512, SMEM_REQ>>>(x, w_o, b_o, sigma, out);
}

// round 15
// speedup vs baseline: 1.1417x; 1.1417x over previous
#include <cuda_runtime.h>
#include <cuda_bf16.h>
#include <cstdint>

#define B_   16
#define C_   64
#define H_   64
#define W_   64
#define N_   4096
#define M_   1024
#define D8   8
#define D2   32
#define CH48 48

// Device scratch (no cudaMalloc allowed)
__device__ uint32_t d_thp[B_ * 8 * N_];          // theta pre-scaled tf32 bits
__device__ uint32_t d_phip[B_ * M_ * 8];         // phi pre-packed tf32 frag slots
__device__ uint32_t d_gp[B_ * D2 * M_ / 2];      // g pre-packed bf16x2 frag slots

// ---- f32x2 packed helpers ---------------------------------------------------
__device__ __forceinline__ void ffma2(unsigned long long& d,
                                      unsigned long long a,
                                      unsigned long long b) {
    asm("fma.rn.f32x2 %0, %1, %2, %0;" : "+l"(d) : "l"(a), "l"(b));
}
__device__ __forceinline__ unsigned long long pack_ff(float lo, float hi) {
    unsigned long long r;
    asm("mov.b64 %0, {%1,%2};" : "=l"(r) : "f"(lo), "f"(hi));
    return r;
}
__device__ __forceinline__ unsigned long long pack_rr(uint32_t lo, uint32_t hi) {
    unsigned long long r;
    asm("mov.b64 %0, {%1,%2};" : "=l"(r) : "r"(lo), "r"(hi));
    return r;
}
__device__ __forceinline__ void unpack_ff(unsigned long long v, float& lo, float& hi) {
    asm("mov.b64 {%0,%1}, %2;" : "=f"(lo), "=f"(hi) : "l"(v));
}

// ---- mma wrappers (baseline PTX, legal on plain sm_103) ----------------------
__device__ __forceinline__ void mma16816(float& d0, float& d1, float& d2, float& d3,
                                         uint32_t a0, uint32_t a1, uint32_t a2, uint32_t a3,
                                         uint32_t b0, uint32_t b1) {
    asm volatile(
        "mma.sync.aligned.m16n8k16.row.col.f32.bf16.bf16.f32 "
        "{%0,%1,%2,%3}, {%4,%5,%6,%7}, {%8,%9}, {%0,%1,%2,%3};"
        : "+f"(d0), "+f"(d1), "+f"(d2), "+f"(d3)
        : "r"(a0), "r"(a1), "r"(a2), "r"(a3), "r"(b0), "r"(b1));
}
__device__ __forceinline__ void mma1688_tf32(float& d0, float& d1, float& d2, float& d3,
                                             uint32_t a0, uint32_t a1, uint32_t a2, uint32_t a3,
                                             uint32_t b0, uint32_t b1) {
    asm volatile(
        "mma.sync.aligned.m16n8k8.row.col.f32.tf32.tf32.f32 "
        "{%0,%1,%2,%3}, {%4,%5,%6,%7}, {%8,%9}, {%0,%1,%2,%3};"
        : "+f"(d0), "+f"(d1), "+f"(d2), "+f"(d3)
        : "r"(a0), "r"(a1), "r"(a2), "r"(a3), "r"(b0), "r"(b1));
}
__device__ __forceinline__ uint32_t to_tf32(float v) {
    uint32_t r;
    asm("cvt.rna.tf32.f32 %0, %1;" : "=r"(r) : "f"(v));
    return r;
}
__device__ __forceinline__ uint32_t bf16x2_of(float lo, float hi) {
    uint32_t r;
    asm("cvt.rn.bf16x2.f32 %0, %1, %2;" : "=r"(r) : "f"(hi), "f"(lo));
    return r;
}
__device__ __forceinline__ float ex2f(float v) {
    float r;
    asm("ex2.approx.f32 %0, %1;" : "=f"(r) : "f"(v));
    return r;
}

// ---------------------------------------------------------------------------
// P1: FUSED conv1x1 + 2x2 maxpool + frag packing (R13 two-pass, PROVEN).
// theta now stored pre-scaled by log2e as tf32 bits (u64-packed stores).
// ---------------------------------------------------------------------------
__global__ void __launch_bounds__(256) convpool_kernel(
    const float* __restrict__ x,
    const float* __restrict__ w_theta, const float* __restrict__ b_theta,
    const float* __restrict__ w_phi,   const float* __restrict__ b_phi,
    const float* __restrict__ w_g,     const float* __restrict__ b_g)
{
    __shared__ float w_s[C_ * 24];
    __shared__ float bias_s[24];
    int tid    = threadIdx.x;
    int chbase = blockIdx.y * 24;

    for (int i = tid; i < C_ * 24; i += 256) {
        int c = i / 24, chp = i % 24;
        int ch = chbase + chp;
        float v;
        if (ch < 8)       v = w_theta[ch * C_ + c];
        else if (ch < 16) v = w_phi[(ch - 8) * C_ + c];
        else              v = w_g[(ch - 16) * C_ + c];
        w_s[i] = v;
    }
    if (tid < 24) {
        int ch = chbase + tid;
        bias_s[tid] = (ch < 8) ? b_theta[ch]
                    : (ch < 16 ? b_phi[ch - 8] : b_g[ch - 16]);
    }
    __syncthreads();

    int idx = blockIdx.x * 256 + tid;
    int b  = idx >> 10;
    int q  = idx & 1023;           // q == m (pooled index)
    int mh = q >> 5, mw = q & 31;
    int n00 = (2 * mh) * W_ + 2 * mw;

    unsigned long long accR0[24], accR1[24];
    #pragma unroll
    for (int j = 0; j < 24; j++) {
        unsigned long long bb = pack_ff(bias_s[j], bias_s[j]);
        accR0[j] = bb; accR1[j] = bb;
    }

    const float* xb = x + ((size_t)b * C_) * N_ + n00;
    #pragma unroll 4
    for (int c = 0; c < C_; c++) {
        unsigned long long x0 = *(const unsigned long long*)(xb + (size_t)c * N_);
        unsigned long long x1 = *(const unsigned long long*)(xb + (size_t)c * N_ + W_);
        const float* wrow = w_s + c * 24;
        #pragma unroll
        for (int j = 0; j < 24; j++) {
            float wj = wrow[j];
            unsigned long long w2 = pack_ff(wj, wj);
            ffma2(accR0[j], x0, w2);
            ffma2(accR1[j], x1, w2);
        }
    }

    int m = q;
    int r = m & 15;
    uint32_t gslot = (uint32_t)((m & ~15) * 2 + ((r >> 1) & 3) * 8 + (r >> 3) * 4);
    bool even = (m & 1) == 0;

    if (chbase == 0) {
        // theta: store pre-scaled tf32 bits (all 4 positions)
        uint32_t* tb = d_thp + (size_t)b * 8 * N_ + n00;
        const float sc = 1.4426950408889634f;
        #pragma unroll
        for (int ch = 0; ch < 8; ch++) {
            float a0, a1, c0, c1;
            unpack_ff(accR0[ch], a0, a1);
            unpack_ff(accR1[ch], c0, c1);
            *(unsigned long long*)(tb + (size_t)ch * N_)
                = pack_rr(to_tf32(a0 * sc), to_tf32(a1 * sc));
            *(unsigned long long*)(tb + (size_t)ch * N_ + W_)
                = pack_rr(to_tf32(c0 * sc), to_tf32(c1 * sc));
        }
        // phi ch8-15: maxpool -> tf32 packed slot
        #pragma unroll
        for (int ch = 8; ch < 16; ch++) {
            float a0, a1, b0, b1;
            unpack_ff(accR0[ch], a0, a1);
            unpack_ff(accR1[ch], b0, b1);
            float v = fmaxf(fmaxf(a0, a1), fmaxf(b0, b1));
            int d = ch - 8;
            d_phip[b * 8192 + m * 8 + (d & 3) * 2 + (d >> 2)] = to_tf32(v);
        }
        // g ch0-7: maxpool -> bf16x2 pair slot
        #pragma unroll
        for (int ch = 16; ch < 24; ch++) {
            float a0, a1, b0, b1;
            unpack_ff(accR0[ch], a0, a1);
            unpack_ff(accR1[ch], b0, b1);
            float v = fmaxf(fmaxf(a0, a1), fmaxf(b0, b1));
            float v1 = __shfl_down_sync(0xffffffffu, v, 1);
            if (even) {
                __nv_bfloat162 h = __floats2bfloat162_rn(v, v1);
                uint32_t byte = (uint32_t)(b * 32 + (ch - 16)) * 2048 + gslot;
                d_gp[byte >> 2] = *(uint32_t*)&h;
            }
        }
    } else {
        // g ch8-31
        #pragma unroll
        for (int chp = 0; chp < 24; chp++) {
            float a0, a1, b0, b1;
            unpack_ff(accR0[chp], a0, a1);
            unpack_ff(accR1[chp], b0, b1);
            float v = fmaxf(fmaxf(a0, a1), fmaxf(b0, b1));
            float v1 = __shfl_down_sync(0xffffffffu, v, 1);
            if (even) {
                __nv_bfloat162 h = __floats2bfloat162_rn(v, v1);
                uint32_t byte = (uint32_t)(b * 32 + 8 + chp) * 2048 + gslot;
                d_gp[byte >> 2] = *(uint32_t*)&h;
            }
        }
    }
}

// ---------------------------------------------------------------------------
// Main kernel (R13 winner) + f32x2 epilogue (halves projection math issue).
// ---------------------------------------------------------------------------
#define GS3    2080                         // smem g row stride bytes
#define OFF_G    0                          // 32*2080 = 66560
#define OFF_PHI  66560                      // 32768 -> 99328
#define OFF_WO   99328                      // 8192  -> 107520
#define OFF_BO   107520                     // 256   -> 107776
#define OFF_AG   0                          // alias G (dead after loop)
#define SMEM_REQ 107776

__global__ void __launch_bounds__(512, 2) attn_main_kernel(
    const float* __restrict__ x,
    const float* __restrict__ w_o,
    const float* __restrict__ b_o,
    const float* __restrict__ sigma,
    float* __restrict__ out)
{
    extern __shared__ char smp[];
    float* wo_s = (float*)(smp + OFF_WO);
    float* bo_s = (float*)(smp + OFF_BO);
    float* ag_s = (float*)(smp + OFF_AG);

    int tid   = threadIdx.x;
    int warp  = tid >> 5, lane = tid & 31;
    int b     = blockIdx.y;
    int qbase = blockIdx.x * 256;

    int q0 = warp * 16;
    int g  = lane >> 2;
    int tg = lane & 3;

    // theta A-fragments: bare LDGs of pre-converted tf32 bits
    const uint32_t* tsrc = d_thp + (size_t)b * 8 * N_ + qbase;
    uint32_t ta0 = tsrc[(size_t)tg * N_ + q0 + g];
    uint32_t ta1 = tsrc[(size_t)tg * N_ + q0 + g + 8];
    uint32_t ta2 = tsrc[(size_t)(tg + 4) * N_ + q0 + g];
    uint32_t ta3 = tsrc[(size_t)(tg + 4) * N_ + q0 + g + 8];

    // ---- setup: pure memcpy of pre-packed frag data ----
    {
        const uint4* gp = (const uint4*)(d_gp + (size_t)b * 16384);
        for (int i = tid; i < 4096; i += 512) {       // 65536 B
            int c = i >> 7, w = i & 127;
            *(uint4*)(smp + OFF_G + c * GS3 + w * 16) = gp[i];
        }
        const uint4* pp = (const uint4*)(d_phip + (size_t)b * 8192);
        for (int i = tid; i < 2048; i += 512)         // 32768 B
            *(uint4*)(smp + OFF_PHI + i * 16) = pp[i];
        const float4* w4 = (const float4*)w_o;
        float4* ws4 = (float4*)wo_s;
        for (int i = tid; i < 64 * 32 / 4; i += 512) ws4[i] = w4[i];
        if (tid < 64) bo_s[tid] = b_o[tid];
    }
    __syncthreads();

    float rs_lo = 0.f, rs_hi = 0.f;
    float acc[4][4];
    #pragma unroll
    for (int nt = 0; nt < 4; nt++)
        #pragma unroll
        for (int r = 0; r < 4; r++) acc[nt][r] = 0.f;

    // induction pointers (all other offsets are immediates)
    const char* pPhi = smp + OFF_PHI + g * 32 + tg * 8;
    const char* pG   = smp + OFF_G + g * GS3 + tg * 8;

    // ---- 64 units of 16 keys: full K per warp ----
    #pragma unroll 1
    for (int u = 0; u < 64; u++) {
        uint2 p0 = *(const uint2*)(pPhi);
        uint2 p1 = *(const uint2*)(pPhi + 256);
        uint2 g0 = *(const uint2*)(pG);
        uint2 g1 = *(const uint2*)(pG + 8 * GS3);
        uint2 g2 = *(const uint2*)(pG + 16 * GS3);
        uint2 g3 = *(const uint2*)(pG + 24 * GS3);
        pPhi += 512;
        pG   += 32;

        float e0 = 0.f, e1 = 0.f, e2 = 0.f, e3 = 0.f;
        mma1688_tf32(e0, e1, e2, e3, ta0, ta1, ta2, ta3, p0.x, p0.y);
        float f0 = 0.f, f1 = 0.f, f2 = 0.f, f3 = 0.f;
        mma1688_tf32(f0, f1, f2, f3, ta0, ta1, ta2, ta3, p1.x, p1.y);

        e0 = ex2f(e0); e1 = ex2f(e1); e2 = ex2f(e2); e3 = ex2f(e3);
        f0 = ex2f(f0); f1 = ex2f(f1); f2 = ex2f(f2); f3 = ex2f(f3);
        rs_lo += (e0 + e1) + (f0 + f1);
        rs_hi += (e2 + e3) + (f2 + f3);

        uint32_t a0 = bf16x2_of(e0, e1);
        uint32_t a1 = bf16x2_of(e2, e3);
        uint32_t a2 = bf16x2_of(f0, f1);
        uint32_t a3 = bf16x2_of(f2, f3);

        mma16816(acc[0][0], acc[0][1], acc[0][2], acc[0][3], a0, a1, a2, a3, g0.x, g0.y);
        mma16816(acc[1][0], acc[1][1], acc[1][2], acc[1][3], a0, a1, a2, a3, g1.x, g1.y);
        mma16816(acc[2][0], acc[2][1], acc[2][2], acc[2][3], a0, a1, a2, a3, g2.x, g2.y);
        mma16816(acc[3][0], acc[3][1], acc[3][2], acc[3][3], a0, a1, a2, a3, g3.x, g3.y);
    }

    // ---- complete rowsums via quad shuffle ----
    rs_lo += __shfl_xor_sync(0xffffffffu, rs_lo, 1);
    rs_lo += __shfl_xor_sync(0xffffffffu, rs_lo, 2);
    rs_hi += __shfl_xor_sync(0xffffffffu, rs_hi, 1);
    rs_hi += __shfl_xor_sync(0xffffffffu, rs_hi, 2);
    float inv_lo = 1.f / rs_lo;
    float inv_hi = 1.f / rs_hi;

    __syncthreads();   // all warps done reading G/PHI -> AG alias safe

    // normalize in registers, stage AG[q][c]
    #pragma unroll
    for (int nt = 0; nt < 4; nt++) {
        int c0 = nt * 8 + 2 * tg;
        ag_s[(q0 + g) * 36 + c0]         = acc[nt][0] * inv_lo;
        ag_s[(q0 + g) * 36 + c0 + 1]     = acc[nt][1] * inv_lo;
        ag_s[(q0 + g + 8) * 36 + c0]     = acc[nt][2] * inv_hi;
        ag_s[(q0 + g + 8) * 36 + c0 + 1] = acc[nt][3] * inv_hi;
    }
    __syncthreads();

    // ---- projection + residual epilogue: f32x2 (half the FMA issue) ----
    float sig = sigma[0];
    int nl = tid & 255;
    int kh = tid >> 8;

    // AG channel-pairs as direct u64 loads (nl*36 even -> 8B aligned)
    unsigned long long ag2[16];
    #pragma unroll
    for (int c2 = 0; c2 < 16; c2++)
        ag2[c2] = *(const unsigned long long*)(ag_s + nl * 36 + 2 * c2);

    size_t xoff_base = ((size_t)b * C_ + kh * 32) * N_ + qbase + nl;
    #pragma unroll 4
    for (int kk = 0; kk < 32; kk++) {
        int k = kh * 32 + kk;
        const unsigned long long* wrow2 =
            (const unsigned long long*)(wo_s + k * 32);
        unsigned long long accA = pack_ff(bo_s[k], 0.f);
        unsigned long long accB = 0ull;
        #pragma unroll
        for (int c2 = 0; c2 < 8; c2++) {
            ffma2(accA, wrow2[2 * c2],     ag2[2 * c2]);
            ffma2(accB, wrow2[2 * c2 + 1], ag2[2 * c2 + 1]);
        }
        float a0, a1, b0v, b1v;
        unpack_ff(accA, a0, a1);
        unpack_ff(accB, b0v, b1v);
        float val = (a0 + a1) + (b0v + b1v);
        size_t off = xoff_base + (size_t)kk * N_;
        out[off] = x[off] + sig * val;
    }
}

// ---------------------------------------------------------------------------
extern "C" void kernel_launch(void* const* d_in, const int* in_sizes, int n_in,
                              void* d_out, int out_size)
{
    const float* x       = (const float*)d_in[0];
    const float* w_theta = (const float*)d_in[1];
    const float* b_theta = (const float*)d_in[2];
    const float* w_phi   = (const float*)d_in[3];
    const float* b_phi   = (const float*)d_in[4];
    const float* w_g     = (const float*)d_in[5];
    const float* b_g     = (const float*)d_in[6];
    const float* w_o     = (const float*)d_in[7];
    const float* b_o     = (const float*)d_in[8];
    const float* sigma   = (const float*)d_in[9];
    float* out = (float*)d_out;

    convpool_kernel<<<dim3(B_ * 1024 / 256, 2), 256>>>(x, w_theta, b_theta,
                                                       w_phi, b_phi, w_g, b_g);

    cudaFuncSetAttribute(attn_main_kernel,
                         cudaFuncAttributeMaxDynamicSharedMemorySize, SMEM_REQ);
    attn_main_kernel<<<dim3(N_ / 256, B_), 512, SMEM_REQ>>>(x, w_o, b_o, sigma, out);
}